// round 15
// baseline (speedup 1.0000x reference)
#include <cuda_runtime.h>
#include <cuda_bf16.h>
#include <cstdint>

#define N_TOK   16384      // B*T
#define EDIM    1024
#define DHEAD   32
#define MFEAT   256

// ---------------- scratch (__device__ globals; no allocation) ----------------
// W combined [64 n][1024 k] bf16 hi/lo, per 64-K chunk, 16B-chunk swizzled:
// element (c, n, kk) at [c*4096 + n*64 + ((kk/8 ^ (n&7))*8) + (kk&7)]
__device__ __nv_bfloat16 W_hi_g[16 * 64 * 64];
__device__ __nv_bfloat16 W_lo_g[16 * 64 * 64];

__device__ __forceinline__ uint32_t smem_u32(const void* p) {
    uint32_t a;
    asm("{ .reg .u64 t; cvta.to.shared.u64 t, %1; cvt.u32.u64 %0, t; }" : "=r"(a) : "l"(p));
    return a;
}
__device__ __forceinline__ void ldsm_x4(uint32_t& r0, uint32_t& r1, uint32_t& r2, uint32_t& r3, uint32_t a) {
    asm volatile("ldmatrix.sync.aligned.m8n8.x4.shared.b16 {%0,%1,%2,%3}, [%4];"
                 : "=r"(r0), "=r"(r1), "=r"(r2), "=r"(r3) : "r"(a));
}
__device__ __forceinline__ void ldsm_x2(uint32_t& r0, uint32_t& r1, uint32_t a) {
    asm volatile("ldmatrix.sync.aligned.m8n8.x2.shared.b16 {%0,%1}, [%2];"
                 : "=r"(r0), "=r"(r1) : "r"(a));
}
__device__ __forceinline__ void mma_bf16(float* c, const uint32_t* a, uint32_t b0, uint32_t b1) {
    asm volatile("mma.sync.aligned.m16n8k16.row.col.f32.bf16.bf16.f32 "
                 "{%0,%1,%2,%3}, {%4,%5,%6,%7}, {%8,%9}, {%0,%1,%2,%3};"
                 : "+f"(c[0]), "+f"(c[1]), "+f"(c[2]), "+f"(c[3])
                 : "r"(a[0]), "r"(a[1]), "r"(a[2]), "r"(a[3]), "r"(b0), "r"(b1));
}
__device__ __forceinline__ void cvtpair(float x, float y, uint32_t& h, uint32_t& l) {
    __nv_bfloat162 hh = __float22bfloat162_rn(make_float2(x, y));
    float2 f = __bfloat1622float2(hh);
    __nv_bfloat162 ll = __float22bfloat162_rn(make_float2(x - f.x, y - f.y));
    h = *(uint32_t*)&hh;
    l = *(uint32_t*)&ll;
}
__device__ __forceinline__ void cp_async16(uint32_t dst, const void* src) {
    asm volatile("cp.async.cg.shared.global [%0], [%1], 16;" :: "r"(dst), "l"(src) : "memory");
}
#define CP_COMMIT()  asm volatile("cp.async.commit_group;" ::: "memory")
#define CP_WAIT(n)   asm volatile("cp.async.wait_group %0;" :: "n"(n) : "memory")
#define BAR_SET(id)  asm volatile("bar.sync %0, %1;" :: "r"(id), "r"(256) : "memory")

// ---------------- kernel 0: W -> bf16 hi/lo, chunk-swizzled ------------------
__global__ __launch_bounds__(256) void wprep_kernel(
    const float* __restrict__ Wq, const float* __restrict__ Wk)
{
    int idx  = blockIdx.x * 256 + threadIdx.x;   // 0..16383
    int c    = idx >> 10;
    int rest = idx & 1023;
    int kk   = rest >> 4;
    int ng   = rest & 15;                        // group of 4 n
    int k    = c * 64 + kk;
    float4 v = (ng < 8) ? ((const float4*)Wq)[k * 8 + ng]
                        : ((const float4*)Wk)[k * 8 + (ng - 8)];
    const float* vp = &v.x;
    #pragma unroll
    for (int e = 0; e < 4; e++) {
        int n = ng * 4 + e;
        float f = vp[e];
        __nv_bfloat16 h = __float2bfloat16(f);
        __nv_bfloat16 l = __float2bfloat16(f - __bfloat162float(h));
        int pos = c * 4096 + n * 64 + (((kk >> 3) ^ (n & 7)) << 3) + (kk & 7);
        W_hi_g[pos] = h;
        W_lo_g[pos] = l;
    }
}

// ---------------- fused kernel: in-CTA split-K projection + features --------
// 512 thr / 16 warps, M=128 tokens/CTA, grid 128.
// Set s = warps 8s..8s+7 handles K half [s*512, s*512+512) with its own
// A/B smem + named barrier -> 4 warps/SMSP latency hiding at 1.33 wf/MMA.
// Exchange: partial q/k summed via smem (zqA+zqB+bias); feat on 16 warps.
#define SM_A      0              // set s: s*32768 (hi +0, lo +16384) = 64KB
#define SM_B      65536          // set s: 65536 + s*32768, 2 bufs x 16K = 64KB
#define SM_WSH    65536          // phase2 alias over B: uint32[256*20]
#define SM_WSL    86016
#define SMEM_SZ   131072

__global__ __launch_bounds__(512, 1) void fused_kernel(
    const float* __restrict__ x,
    const float* __restrict__ bq, const float* __restrict__ bk,
    const float* __restrict__ w, float* __restrict__ out)
{
    extern __shared__ __align__(16) char sm[];
    // phase-2 aliases
    float* zqA = (float*)(sm);               // 128x32 f32 partial q, set 0
    float* zkA = (float*)(sm + 16384);
    float* zqB = (float*)(sm + 32768);       // set 1
    float* zkB = (float*)(sm + 49152);
    uint32_t* wsh = (uint32_t*)(sm + SM_WSH);
    uint32_t* wsl = (uint32_t*)(sm + SM_WSL);

    const int tid = threadIdx.x;
    const int lid = tid & 31;
    const int set = tid >> 8;              // 0 or 1
    const int ts  = tid & 255;             // thread id within set
    const int wid_s = ts >> 5;             // warp id within set 0..7
    const int row0 = blockIdx.x * 128;
    const int kbase = set * 512;

    const uint32_t smb = smem_u32(sm);
    const uint32_t sA = smb + set * 32768;           // hi +0, lo +16384
    const uint32_t sBset = smb + SM_B + set * 32768; // buf b: +b*16384

    char* Aset = sm + set * 32768;

    const int mw = (wid_s >> 1) * 32;      // warp's 32-row block
    const int h  = wid_s & 1;              // dim-half

    float acc[2][4][4];
    #pragma unroll
    for (int ms = 0; ms < 2; ms++)
        #pragma unroll
        for (int j = 0; j < 4; j++)
            acc[ms][j][0] = acc[ms][j][1] = acc[ms][j][2] = acc[ms][j][3] = 0.f;

    // x staging: 1024 8-float groups over 256 set-threads -> 4 groups/thread
    int cr[4], cc8[4];
    #pragma unroll
    for (int i = 0; i < 4; i++) {
        int idx = i * 256 + ts;
        cr[i]  = idx >> 3;                 // row 0..127
        cc8[i] = idx & 7;
    }
    // ldmatrix lane geometry
    const int i4   = lid >> 3;
    const int arow_off = ((i4 & 1) << 3) + (lid & 7);
    const int l7   = lid & 7;
    const int achunk_add = i4 >> 1;
    const int b_i  = (lid >> 3) & 1;

    // ---- prologue: cp.async B chunk (set*8) into buf 0 ----
    {
        size_t gb = (size_t)(set * 8) * 8192;
        #pragma unroll
        for (int i = 0; i < 2; i++) {
            int u = i * 256 + ts;
            cp_async16(sBset + u * 16,        (const char*)W_hi_g + gb + u * 16);
            cp_async16(sBset + 8192 + u * 16, (const char*)W_lo_g + gb + u * 16);
        }
        CP_COMMIT();
    }

    // ================= mainloop: 8 chunks of K=64 =================
    #pragma unroll 1
    for (int c = 0; c < 8; c++) {
        // LDG + convert + stage x chunk (cross-warp overlap hides latency)
        #pragma unroll
        for (int i = 0; i < 4; i++) {
            const float4* p = (const float4*)&x[(size_t)(row0 + cr[i]) * EDIM + kbase + c * 64 + cc8[i] * 8];
            float4 v0 = p[0], v1 = p[1];
            uint4 H, L;
            cvtpair(v0.x, v0.y, H.x, L.x);
            cvtpair(v0.z, v0.w, H.y, L.y);
            cvtpair(v1.x, v1.y, H.z, L.z);
            cvtpair(v1.z, v1.w, H.w, L.w);
            uint32_t off = (uint32_t)(cr[i] * 128 + ((cc8[i] ^ (cr[i] & 7)) << 4));
            *(uint4*)(Aset + off) = H;
            *(uint4*)(Aset + 16384 + off) = L;
        }
        if (c < 7) {
            const uint32_t db = sBset + ((c + 1) & 1) * 16384;
            const size_t gb = (size_t)(set * 8 + c + 1) * 8192;
            #pragma unroll
            for (int i = 0; i < 2; i++) {
                int u = i * 256 + ts;
                cp_async16(db + u * 16,        (const char*)W_hi_g + gb + u * 16);
                cp_async16(db + 8192 + u * 16, (const char*)W_lo_g + gb + u * 16);
            }
            CP_COMMIT();
            CP_WAIT(1);      // B_c arrived (own copies); barrier publishes all
        } else {
            CP_WAIT(0);
        }
        BAR_SET(1 + set);

        // MMA: 4 k16-groups x 4 n-tiles x 2 m-subtiles x 3 passes
        const uint32_t sBh = sBset + (c & 1) * 16384;
        const uint32_t sBl = sBh + 8192;
        #pragma unroll
        for (int gk = 0; gk < 4; gk++) {
            uint32_t ah4[2][4], al4[2][4];
            #pragma unroll
            for (int ms = 0; ms < 2; ms++) {
                uint32_t aoff = (uint32_t)((mw + 16 * ms + arow_off) * 128
                               + (((2 * gk + achunk_add) ^ l7) << 4));
                ldsm_x4(ah4[ms][0], ah4[ms][1], ah4[ms][2], ah4[ms][3], sA + aoff);
                ldsm_x4(al4[ms][0], al4[ms][1], al4[ms][2], al4[ms][3], sA + 16384 + aoff);
            }
            #pragma unroll
            for (int jj = 0; jj < 4; jj++) {
                const int tile = (jj < 2) ? (2 * h + jj) : (2 + 2 * h + jj);
                uint32_t boff = (uint32_t)((8 * tile + l7) * 128 + (((2 * gk + b_i) ^ l7) << 4));
                uint32_t bh0, bh1, bl0, bl1;
                ldsm_x2(bh0, bh1, sBh + boff);
                ldsm_x2(bl0, bl1, sBl + boff);
                #pragma unroll
                for (int ms = 0; ms < 2; ms++) {
                    mma_bf16(acc[ms][jj], ah4[ms], bh0, bh1);
                    mma_bf16(acc[ms][jj], ah4[ms], bl0, bl1);
                    mma_bf16(acc[ms][jj], al4[ms], bh0, bh1);
                }
            }
        }
        BAR_SET(1 + set);
    }

    // ============ exchange: partial q,k (NO bias) -> own zq/zk region ========
    const int g = lid >> 2, t = lid & 3;
    {
        float* zq = (float*)(sm + set * 32768);
        float* zk = (float*)(sm + set * 32768 + 16384);
        #pragma unroll
        for (int ms = 0; ms < 2; ms++) {
            const int lr0 = mw + 16 * ms + g, lr1 = lr0 + 8;
            #pragma unroll
            for (int jj = 0; jj < 2; jj++) {      // q tiles
                int col = 16 * h + 8 * jj + 2 * t;
                *(float2*)&zq[lr0 * 32 + col] = make_float2(acc[ms][jj][0], acc[ms][jj][1]);
                *(float2*)&zq[lr1 * 32 + col] = make_float2(acc[ms][jj][2], acc[ms][jj][3]);
            }
            #pragma unroll
            for (int jj = 2; jj < 4; jj++) {      // k tiles
                int col = 16 * h + 8 * (jj - 2) + 2 * t;
                *(float2*)&zk[lr0 * 32 + col] = make_float2(acc[ms][jj][0], acc[ms][jj][1]);
                *(float2*)&zk[lr1 * 32 + col] = make_float2(acc[ms][jj][2], acc[ms][jj][3]);
            }
        }
    }
    __syncthreads();
    // w tables over dead B region (threads 0-255, one row each)
    if (tid < 256) {
        const int row = tid;
        #pragma unroll
        for (int j = 0; j < 8; j++) {
            float4 v = *(const float4*)&w[(size_t)row * DHEAD + 4 * j];
            uint32_t h0, l0, h1, l1;
            cvtpair(v.x, v.y, h0, l0);
            cvtpair(v.z, v.w, h1, l1);
            wsh[row * 20 + 2 * j]     = h0;
            wsh[row * 20 + 2 * j + 1] = h1;
            wsl[row * 20 + 2 * j]     = l0;
            wsl[row * 20 + 2 * j + 1] = l1;
        }
    }
    __syncthreads();

    // ============ rebuild feat A-frags + s (sum partials + bias) ============
    // 16 warps: rows ((wid&7)*16), n-half (wid>>3)*128
    const int fw = tid >> 5;
    const int lr0 = (fw & 7) * 16 + g, lr1 = lr0 + 8;
    const int nhalf = (fw >> 3) * 128;
    uint32_t ah[2][4], al[2][4];
    float s0 = 0.f, s1 = 0.f;
    #pragma unroll
    for (int kg = 0; kg < 2; kg++) {
        #pragma unroll
        for (int hh = 0; hh < 2; hh++) {
            int col = kg * 16 + hh * 8 + 2 * t;
            float2 bq2 = *(const float2*)&bq[col];
            float2 bk2 = *(const float2*)&bk[col];
            float2 qa0 = *(const float2*)&zqA[lr0 * 32 + col];
            float2 qb0 = *(const float2*)&zqB[lr0 * 32 + col];
            float2 ka0 = *(const float2*)&zkA[lr0 * 32 + col];
            float2 kb0 = *(const float2*)&zkB[lr0 * 32 + col];
            float2 qa1 = *(const float2*)&zqA[lr1 * 32 + col];
            float2 qb1 = *(const float2*)&zqB[lr1 * 32 + col];
            float2 ka1 = *(const float2*)&zkA[lr1 * 32 + col];
            float2 kb1 = *(const float2*)&zkB[lr1 * 32 + col];
            float q00 = qa0.x + qb0.x + bq2.x, q01 = qa0.y + qb0.y + bq2.y;
            float k00 = ka0.x + kb0.x + bk2.x, k01 = ka0.y + kb0.y + bk2.y;
            float q10 = qa1.x + qb1.x + bq2.x, q11 = qa1.y + qb1.y + bq2.y;
            float k10 = ka1.x + kb1.x + bk2.x, k11 = ka1.y + kb1.y + bk2.y;
            s0 += q00 * q00 + q01 * q01 + k00 * k00 + k01 * k01;
            s1 += q10 * q10 + q11 * q11 + k10 * k10 + k11 * k11;
            cvtpair(q00 + k00, q01 + k01, ah[kg][2 * hh],     al[kg][2 * hh]);
            cvtpair(q10 + k10, q11 + k11, ah[kg][2 * hh + 1], al[kg][2 * hh + 1]);
        }
    }
    s0 += __shfl_xor_sync(0xffffffffu, s0, 1);
    s0 += __shfl_xor_sync(0xffffffffu, s0, 2);
    s1 += __shfl_xor_sync(0xffffffffu, s1, 1);
    s1 += __shfl_xor_sync(0xffffffffu, s1, 2);
    s0 *= 0.5f;
    s1 *= 0.5f;

    // ============ phase 2: features (16 n-tiles per warp) ============
    const int r0 = row0 + lr0;
    #pragma unroll 4
    for (int j = 0; j < 16; j++) {
        const int nb = nhalf + 8 * j;
        const uint32_t* bhp = &wsh[(nb + g) * 20 + t];
        const uint32_t* blp = &wsl[(nb + g) * 20 + t];
        uint32_t bh0 = bhp[0], bh1 = bhp[4], bh2 = bhp[8], bh3 = bhp[12];
        uint32_t bl0 = blp[0], bl1 = blp[4], bl2 = blp[8], bl3 = blp[12];

        float c[4] = {0.f, 0.f, 0.f, 0.f};
        mma_bf16(c, ah[0], bh0, bh1);   // hi*hi
        mma_bf16(c, ah[1], bh2, bh3);
        mma_bf16(c, ah[0], bl0, bl1);   // hi*lo
        mma_bf16(c, ah[1], bl2, bl3);
        mma_bf16(c, al[0], bh0, bh1);   // lo*hi
        mma_bf16(c, al[1], bh2, bh3);

        float r00 = 0.5f * (__expf(c[0] - s0) + __expf(-c[0] - s0));
        float r01 = 0.5f * (__expf(c[1] - s0) + __expf(-c[1] - s0));
        float r10 = 0.5f * (__expf(c[2] - s1) + __expf(-c[2] - s1));
        float r11 = 0.5f * (__expf(c[3] - s1) + __expf(-c[3] - s1));
        *(float2*)&out[(size_t)r0 * MFEAT + nb + 2 * t]       = make_float2(r00, r01);
        *(float2*)&out[(size_t)(r0 + 8) * MFEAT + nb + 2 * t] = make_float2(r10, r11);
    }
}

extern "C" void kernel_launch(void* const* d_in, const int* in_sizes, int n_in,
                              void* d_out, int out_size)
{
    const float* x  = (const float*)d_in[0];
    const float* Wq = (const float*)d_in[1];
    const float* bq = (const float*)d_in[2];
    const float* Wk = (const float*)d_in[3];
    const float* bk = (const float*)d_in[4];
    // d_in[5], d_in[6] = Wv, bv: unused (reference discards v)
    const float* w  = (const float*)d_in[7];
    float* out = (float*)d_out;

    static bool attr_set = false;   // idempotent host-side attribute
    if (!attr_set) {
        cudaFuncSetAttribute(fused_kernel, cudaFuncAttributeMaxDynamicSharedMemorySize, SMEM_SZ);
        attr_set = true;
    }
    wprep_kernel<<<64, 256>>>(Wq, Wk);
    fused_kernel<<<N_TOK / 128, 512, SMEM_SZ>>>(x, bq, bk, w, out);
}